// round 14
// baseline (speedup 1.0000x reference)
#include <cuda_runtime.h>

#define BB   256
#define TT   1024
#define SS   7
#define HH   64
#define LL   4
#define OO   3
#define UU   4
#define BETA 0.8f
#define TH   1.0f
#define NEPOCH (TT / UU)      // 256
#define ROWF   64             // spike row: 64 floats (uniform broadcast reads; no pad needed)

// Named-barrier rendezvous. id 0 reserved for __syncthreads.
__device__ __forceinline__ void nbar(int id, int nthreads) {
    asm volatile("bar.sync %0, %1;" :: "r"(id), "r"(nthreads) : "memory");
}

// 32-element dot product: spike chunk x register weight row.
// All lanes of the calling warp pass the SAME sp -> every LDS.128 is a
// single-address broadcast = 1 L1 wavefront.
__device__ __forceinline__ float dot32(const float* __restrict__ sp,
                                       const float* __restrict__ wrow) {
    float a0 = 0.f, a1 = 0.f;
    #pragma unroll
    for (int i = 0; i < 8; i++) {
        float4 sv = *(const float4*)(sp + 4 * i);
        a0 = fmaf(sv.x, wrow[4 * i + 0], a0);
        a1 = fmaf(sv.y, wrow[4 * i + 1], a1);
        a0 = fmaf(sv.z, wrow[4 * i + 2], a0);
        a1 = fmaf(sv.w, wrow[4 * i + 3], a1);
    }
    return a0 + a1;
}

// One CTA per batch element, 544 threads (17 warps), 2 CTAs/SM.
// Warps 0..15: warp w = (layer l = w>>2, h-group hg = (w>>1)&1, half = w&1).
//   Lane i owns unit h = hg*32 + i. Each thread holds HALF that unit's weight
//   row (32 regs) and computes a 32-FMA partial; since `half` is warp-uniform,
//   all spike LDS are single-address broadcasts (1 wavefront each).
//   half1 warp STSes its 32 partials, pair rendezvous on named barrier
//   (id = 1 + (l-1)*2 + hg), half0 warp adds them and runs the membrane chain
//   + fully-coalesced spike/hidden stores. half1 keeps no membrane state.
//   Layer 0 (7 inputs): half0 warps do the full 7-FMA dot from warp-uniform
//   x reads; layer-0 half1 warps idle.
// Warp 16 lanes 0..5: output layer, lane-pair half-split + shfl (as before).
// Pipeline over epochs of UU=4 timesteps, double-buffered spikes, one
// __syncthreads per epoch.
__global__ __launch_bounds__(544, 2)
void snn_uni_kernel(const float* __restrict__ x,
                    const float* __restrict__ hidden0,
                    const float* __restrict__ w1,
                    const float* __restrict__ b1,
                    const float* __restrict__ w_h,
                    const float* __restrict__ b_h,
                    const float* __restrict__ w_out,
                    const float* __restrict__ b_out,
                    float* __restrict__ out_outputs,   // [B,T,OO]
                    float* __restrict__ out_hidden,    // [B,T,LL,HH]
                    float* __restrict__ out_xcopy)     // [B,T,SS]
{
    const int b    = blockIdx.x;
    const int tid  = threadIdx.x;
    const int w    = tid >> 5;
    const int lane = tid & 31;

    __shared__ __align__(16) float spk[2][LL][UU][ROWF];
    __shared__ float part[LL - 1][2][UU][32];   // half1 partials: [l-1][hg][k][lane]

    // ---- copy this batch's x slice to the output buffer (coalesced float4) ----
    {
        const float4* xs4 = (const float4*)(x + (size_t)b * TT * SS);
        float4*       xo4 = (float4*)(out_xcopy + (size_t)b * TT * SS);
        const int n4 = TT * SS / 4;  // 1792
        for (int i = tid; i < n4; i += blockDim.x) xo4[i] = xs4[i];
    }

    const bool is_layer = (w < 16);
    const int  l    = w >> 2;
    const int  hg   = (w >> 1) & 1;
    const int  half = w & 1;
    const int  h    = hg * 32 + lane;

    float wrow[32];
    float w0[SS];
    float bias = 0.0f;
    float m    = 0.0f;

    if (is_layer) {
        if (l == 0) {
            if (half == 0) {
                m = hidden0[(size_t)b * TT * LL * HH + h];
                #pragma unroll
                for (int k = 0; k < SS; k++) w0[k] = w1[h * SS + k];
                bias = b1[h];
            }
        } else {
            const float* row = w_h + ((size_t)(l - 1) * HH + h) * HH + half * 32;
            #pragma unroll
            for (int i = 0; i < 32; i++) wrow[i] = row[i];
            if (half == 0) {
                m    = hidden0[(size_t)b * TT * LL * HH + (size_t)l * HH + h];
                bias = b_h[(l - 1) * HH + h];
            }
        }
    } else if (lane < 2 * OO) {
        const int oj = lane >> 1;
        const int oh = lane & 1;
        const float* row = w_out + (size_t)oj * HH + oh * 32;
        #pragma unroll
        for (int i = 0; i < 32; i++) wrow[i] = row[i];
        bias = b_out[oj];
    }

    __syncthreads();

    const float* xrow   = x + (size_t)b * TT * SS;
    float*       hidptr = out_hidden + (size_t)b * TT * LL * HH
                          + (is_layer ? (l * HH + h) : 0);
    float*       outptr = out_outputs + (size_t)b * TT * OO
                          + (!is_layer ? (lane >> 1) : 0);

    int buf = 0;
    for (int e = 0; e < NEPOCH + LL; e++) {
        if (is_layer) {
            if (e >= l && e < l + NEPOCH) {
                if (l == 0) {
                    if (half == 0) {
                        #pragma unroll
                        for (int k = 0; k < UU; k++) {
                            const float* xr = xrow + k * SS;   // warp-uniform LDG
                            float c = bias;
                            #pragma unroll
                            for (int j = 0; j < SS; j++) c = fmaf(xr[j], w0[j], c);
                            const float reset = (m > TH) ? TH : 0.0f;
                            const float m_new = fmaf(BETA, m, c) - reset;
                            m = m_new;
                            spk[buf][0][k][h] = (m_new > TH) ? 1.0f : 0.0f;
                            hidptr[(size_t)k * (LL * HH)] = m_new;
                        }
                        xrow   += UU * SS;
                        hidptr += (size_t)UU * LL * HH;
                    }
                } else {
                    const int pairId = 1 + (l - 1) * 2 + hg;   // 1..6
                    float p[UU];
                    #pragma unroll
                    for (int k = 0; k < UU; k++)
                        p[k] = dot32(&spk[buf ^ 1][l - 1][k][half * 32], wrow);
                    if (half == 1) {
                        #pragma unroll
                        for (int k = 0; k < UU; k++)
                            part[l - 1][hg][k][lane] = p[k];
                        nbar(pairId, 64);
                    } else {
                        nbar(pairId, 64);
                        #pragma unroll
                        for (int k = 0; k < UU; k++) {
                            const float tot = p[k] + part[l - 1][hg][k][lane];
                            const float c   = bias + tot;
                            const float reset = (m > TH) ? TH : 0.0f;
                            const float m_new = fmaf(BETA, m, c) - reset;
                            m = m_new;
                            spk[buf][l][k][h] = (m_new > TH) ? 1.0f : 0.0f;
                            hidptr[(size_t)k * (LL * HH)] = m_new;
                        }
                        hidptr += (size_t)UU * LL * HH;
                    }
                }
            }
        } else if (lane < 2 * OO) {
            if (e >= LL) {
                const int oh = lane & 1;
                #pragma unroll
                for (int k = 0; k < UU; k++) {
                    float pk  = dot32(&spk[buf ^ 1][LL - 1][k][oh * 32], wrow);
                    float tot = pk + __shfl_xor_sync(0x3fu, pk, 1);
                    if (!oh) outptr[k * OO] = bias + tot;
                }
                outptr += UU * OO;
            }
        }
        __syncthreads();
        buf ^= 1;
    }
}

extern "C" void kernel_launch(void* const* d_in, const int* in_sizes, int n_in,
                              void* d_out, int out_size) {
    // metadata order: x, hidden_states, prev_obs, w1, b1, w_h, b_h, w_out, b_out
    const float* x       = (const float*)d_in[0];
    const float* hidden0 = (const float*)d_in[1];
    // d_in[2] = prev_obs (unused by reference)
    const float* w1      = (const float*)d_in[3];
    const float* b1      = (const float*)d_in[4];
    const float* w_h     = (const float*)d_in[5];
    const float* b_h     = (const float*)d_in[6];
    const float* w_out   = (const float*)d_in[7];
    const float* b_out   = (const float*)d_in[8];

    float* out_outputs = (float*)d_out;                                  // B*T*OO
    float* out_hidden  = out_outputs + (size_t)BB * TT * OO;             // B*T*LL*HH
    float* out_xcopy   = out_hidden + (size_t)BB * TT * LL * HH;         // B*T*SS

    snn_uni_kernel<<<BB, 544>>>(x, hidden0, w1, b1, w_h, b_h, w_out, b_out,
                                out_outputs, out_hidden, out_xcopy);
}